// round 11
// baseline (speedup 1.0000x reference)
#include <cuda_runtime.h>
#include <cuda_fp16.h>
#include <cstdint>
#include <cfloat>

// KeyValueBottleneck: b=32, C=64, n=64, dk=dv=16, J=1024
// out = concat(qv[2097152], new_keys[1048576], new_cluster_size[65536], new_keys_avg[1048576])

#define DECAY 0.95f
#define OMD   0.05f
#define EPSV  1e-5f

constexpr int Cc = 64, Nn = 64, DK = 16, J = 1024;
constexpr int OFF_QV   = 0;
constexpr int OFF_KEYS = 2097152;
constexpr int OFF_CS   = OFF_KEYS + Cc * J * DK;  // 3145728
constexpr int OFF_KA   = OFF_CS + Cc * J;         // 3211264

// ---------------- scratch (device globals; no allocation) --------------------
// per key row (32 B): 4 blocks of 8 B indexed by lc: blk[lc] = {w[lc], w[lc+4]}
// (w[i] = fp16 pair for dims 2i,2i+1) -> one LDS.64 per mma B fragment.
__device__ uint2 g_kb[(size_t)Cc * J * 4];   // 2 MB
__device__ float    g_kk[Cc * J];            // -0.5*||k||^2 (fp32, exact bias)
__device__ unsigned g_km[Cc];                // max ||k|| per channel (bits)

__device__ __forceinline__ uint32_t pkhf(float a, float b) {
    __half ha = __float2half(a), hb = __float2half(b);
    return (uint32_t)__half_as_ushort(ha) | ((uint32_t)__half_as_ushort(hb) << 16);
}

// classic tensor-core MMA: m16n8k16, f16 x f16 -> fp32 (sm_80+)
__device__ __forceinline__ void mma16816(float* d, const uint32_t* a,
                                         uint32_t b0, uint32_t b1) {
    asm volatile(
        "mma.sync.aligned.m16n8k16.row.col.f32.f16.f16.f32 "
        "{%0,%1,%2,%3}, {%4,%5,%6,%7}, {%8,%9}, {%0,%1,%2,%3};"
        : "+f"(d[0]), "+f"(d[1]), "+f"(d[2]), "+f"(d[3])
        : "r"(a[0]), "r"(a[1]), "r"(a[2]), "r"(a[3]), "r"(b0), "r"(b1));
}

__device__ __forceinline__ uint32_t smem_u32(const void* p) {
    uint32_t a;
    asm("{ .reg .u64 t; cvta.to.shared.u64 t, %1; cvt.u32.u64 %0, t; }" : "=r"(a) : "l"(p));
    return a;
}
__device__ __forceinline__ void cpasync16(uint32_t smem, const void* g) {
    asm volatile("cp.async.cg.shared.global [%0], [%1], 16;" :: "r"(smem), "l"(g));
}
#define CP_COMMIT() asm volatile("cp.async.commit_group;" ::: "memory")
#define CP_WAIT(n)  asm volatile("cp.async.wait_group %0;" :: "n"(n) : "memory")

// pack score + (1023-j) into low 10 mantissa bits (one LOP3-able expression)
__device__ __forceinline__ float packsj(float s, uint32_t jenc) {
    return __uint_as_float((__float_as_uint(s) & 0xFFFFFC00u) | jenc);
}

// ---------------- kernel 0: EMA seed + key f16-convert (interleaved) ---------
// grid 1344 x 256: [0,1024) ka seed; [1024,1088) cs seed; [1088,1344) keys
__global__ __launch_bounds__(256) void k_prep(const float* __restrict__ keys,
                                              const float* __restrict__ keys_avg,
                                              const float* __restrict__ cs,
                                              float* __restrict__ out) {
    const int b = blockIdx.x, t = threadIdx.x;
    if (b < 1024) {
        int i = b * 256 + t;
        float4 v = ((const float4*)keys_avg)[i];
        v.x *= DECAY; v.y *= DECAY; v.z *= DECAY; v.w *= DECAY;
        ((float4*)out)[OFF_KA / 4 + i] = v;
        return;
    }
    if (b < 1088) {
        int i = (b - 1024) * 256 + t;
        float4 v = ((const float4*)cs)[i];
        v.x *= DECAY; v.y *= DECAY; v.z *= DECAY; v.w *= DECAY;
        ((float4*)out)[OFF_CS / 4 + i] = v;
        return;
    }
    const int row = (b - 1088) * 256 + t;   // 0..65535
    const float4* kr = (const float4*)(keys + (size_t)row * DK);
    float kv[16], kk = 0.f;
#pragma unroll
    for (int q = 0; q < 4; q++) {
        float4 v = kr[q];
        kv[4 * q] = v.x; kv[4 * q + 1] = v.y; kv[4 * q + 2] = v.z; kv[4 * q + 3] = v.w;
        kk += v.x * v.x + v.y * v.y + v.z * v.z + v.w * v.w;
    }
    uint32_t w[8];
#pragma unroll
    for (int d = 0; d < 8; d++) w[d] = pkhf(kv[2 * d], kv[2 * d + 1]);
    uint2* dst = g_kb + (size_t)row * 4;
#pragma unroll
    for (int lc = 0; lc < 4; lc++) dst[lc] = make_uint2(w[lc], w[lc + 4]);
    g_kk[row] = -0.5f * kk;
    float mx = kk;
#pragma unroll
    for (int off = 16; off > 0; off >>= 1)
        mx = fmaxf(mx, __shfl_xor_sync(0xffffffffu, mx, off));
    if ((t & 31) == 0) atomicMax(&g_km[row >> 10], __float_as_uint(sqrtf(mx)));
}

// ---------------- kernel 1: fp16-split 2-MMA screen + 3-level certify --------
// grid = 1024 CTAs (c = bid>>4, mt = bid&15), 256 threads (8 warps).
// Screen = (xhi + xlo).kf16 (fp32 accum, bias init). Scores carry their index in
// the low 10 mantissa bits; top-3 tracked with pure fmin/fmax.
__global__ __launch_bounds__(256) void k_screen(const float* __restrict__ x,
                                                const float* __restrict__ keys,
                                                const float* __restrict__ values,
                                                float* __restrict__ out) {
    __shared__ __align__(16) unsigned char sA[128 * 80];  // [xhi(32B)|xlo(32B)]+pad
    __shared__ __align__(16) unsigned char sB[2][4096];   // dbl-buf 128-key chunks, 32B rows
    __shared__ float skk[J];
    __shared__ float sxn[128];
    __shared__ float sb1[128], sb2[128], sb3[128];

    const int t = threadIdx.x, wid = t >> 5, lane = t & 31;
    const int c = blockIdx.x >> 4, mt = blockIdx.x & 15;
    const int lg = lane >> 2, lc = lane & 3;

    // convert x rows (threads 0..127) + load skk (all 256)
    if (t < 128) {
        const int i0 = mt * 128 + t;
        const int fidx = (((i0 >> 6) * Cc + c) * Nn + (i0 & 63)) * DK;
        const float4* xr = (const float4*)(x + fidx);
        float xv[16], n2 = 0.f;
#pragma unroll
        for (int q = 0; q < 4; q++) {
            float4 v = xr[q];
            xv[4 * q] = v.x; xv[4 * q + 1] = v.y; xv[4 * q + 2] = v.z; xv[4 * q + 3] = v.w;
            n2 += v.x * v.x + v.y * v.y + v.z * v.z + v.w * v.w;
        }
        uint32_t w[16];
#pragma unroll
        for (int d = 0; d < 8; d++) {
            float a = xv[2 * d], bv = xv[2 * d + 1];
            float ah = __half2float(__float2half(a));
            float bh = __half2float(__float2half(bv));
            w[d]     = pkhf(a, bv);           // xhi
            w[8 + d] = pkhf(a - ah, bv - bh); // xlo
        }
        uint4* dst = (uint4*)(sA + t * 80);
#pragma unroll
        for (int q = 0; q < 4; q++)
            dst[q] = make_uint4(w[4 * q], w[4 * q + 1], w[4 * q + 2], w[4 * q + 3]);
        sxn[t] = sqrtf(n2);
    }
    ((float4*)skk)[t] = ((const float4*)(g_kk + c * J))[t];

    // prefetch key chunk 0 (contiguous 4 KB: 256 thr x 16B)
    const uint32_t sb_base = smem_u32(sB);
    const char* kbase = (const char*)(g_kb + (size_t)c * J * 4);
    cpasync16(sb_base + t * 16, kbase + t * 16);
    CP_COMMIT();
    __syncthreads();

    // A fragments: afr[hi/lo][4], rows wid*16..+15 (fp16)
    uint32_t afr[2][4];
#pragma unroll
    for (int ks = 0; ks < 2; ks++) {
        int r0 = wid * 16 + lg;
        int bo = ks * 32 + lc * 4;
        afr[ks][0] = *(const uint32_t*)(sA + r0 * 80 + bo);
        afr[ks][1] = *(const uint32_t*)(sA + (r0 + 8) * 80 + bo);
        afr[ks][2] = *(const uint32_t*)(sA + r0 * 80 + bo + 16);
        afr[ks][3] = *(const uint32_t*)(sA + (r0 + 8) * 80 + bo + 16);
    }

    // per-parity packed top-3 per tracker (ti=0: row lg; ti=1: row lg+8)
    float v1e[2] = {-FLT_MAX, -FLT_MAX}, v2e[2] = {-FLT_MAX, -FLT_MAX}, v3e[2] = {-FLT_MAX, -FLT_MAX};
    float v1o[2] = {-FLT_MAX, -FLT_MAX}, v2o[2] = {-FLT_MAX, -FLT_MAX}, v3o[2] = {-FLT_MAX, -FLT_MAX};

    for (int ch = 0; ch < 8; ch++) {
        if (ch < 7) {
            cpasync16(sb_base + ((ch + 1) & 1) * 4096 + t * 16,
                      kbase + (size_t)(ch + 1) * 4096 + t * 16);
            CP_COMMIT();
            CP_WAIT(1);
        } else {
            CP_WAIT(0);
        }
        __syncthreads();

        const unsigned char* buf = sB[ch & 1] + lg * 32 + lc * 8;
#pragma unroll
        for (int jt = 0; jt < 16; jt++) {
            const uint2 bb = *(const uint2*)(buf + jt * 256);  // 8 rows * 32B
            const int j0 = ch * 128 + jt * 8 + lc * 2;
            const float2 bias = *(const float2*)(skk + j0);
            const uint32_t je_ = 1023 - j0, jo_ = 1022 - j0;

            float d[4] = {bias.x, bias.y, bias.x, bias.y};
            mma16816(d, afr[0], bb.x, bb.y);   // xhi.kf
            mma16816(d, afr[1], bb.x, bb.y);   // xlo.kf

#pragma unroll
            for (int ti = 0; ti < 2; ti++) {
                const float te = packsj(d[2 * ti], je_);
                const float to = packsj(d[2 * ti + 1], jo_);
                float m2c = fminf(te, v1e[ti]);
                v3e[ti] = fmaxf(v3e[ti], fminf(m2c, v2e[ti]));
                v2e[ti] = fmaxf(v2e[ti], m2c);
                v1e[ti] = fmaxf(v1e[ti], te);
                m2c = fminf(to, v1o[ti]);
                v3o[ti] = fmaxf(v3o[ti], fminf(m2c, v2o[ti]));
                v2o[ti] = fmaxf(v2o[ti], m2c);
                v1o[ti] = fmaxf(v1o[ti], to);
            }
        }
        __syncthreads();
    }

    // merge e/o in-thread, then across the 4 lanes of each row-quad (values-only)
    float V1[2], V2[2], V3[2];
#pragma unroll
    for (int ti = 0; ti < 2; ti++) {
        float l1 = fminf(v1e[ti], v1o[ti]), m1 = fmaxf(v1e[ti], v1o[ti]);
        float m2 = fmaxf(v2e[ti], v2o[ti]), l2 = fminf(v2e[ti], v2o[ti]);
        float m3 = fmaxf(v3e[ti], v3o[ti]);
        V1[ti] = m1;
        V2[ti] = fmaxf(l1, m2);
        V3[ti] = fmaxf(fmaxf(fminf(l1, m2), l2), m3);
    }
#pragma unroll
    for (int mask = 1; mask <= 2; mask <<= 1) {
#pragma unroll
        for (int ti = 0; ti < 2; ti++) {
            float w1 = __shfl_xor_sync(0xffffffffu, V1[ti], mask);
            float w2 = __shfl_xor_sync(0xffffffffu, V2[ti], mask);
            float w3 = __shfl_xor_sync(0xffffffffu, V3[ti], mask);
            float l1 = fminf(V1[ti], w1), m1 = fmaxf(V1[ti], w1);
            float m2 = fmaxf(V2[ti], w2), l2 = fminf(V2[ti], w2);
            float m3 = fmaxf(V3[ti], w3);
            V1[ti] = m1;
            V2[ti] = fmaxf(l1, m2);
            V3[ti] = fmaxf(fmaxf(fminf(l1, m2), l2), m3);
        }
    }
    if (lc == 0) {
#pragma unroll
        for (int ti = 0; ti < 2; ti++) {
            int r = wid * 16 + ti * 8 + lg;
            sb1[r] = V1[ti]; sb2[r] = V2[ti]; sb3[r] = V3[ti];
        }
    }
    __syncthreads();

    if (t >= 128) return;  // threads 0..127 own points

    const int i = mt * 128 + t;
    const int fi = (((i >> 6) * Cc + c) * Nn + (i & 63)) * DK;

    const float a1 = sb1[t], a2 = sb2[t], a3 = sb3[t];
    const int c1 = 1023 - (int)(__float_as_uint(a1) & 1023u);
    const int c2 = 1023 - (int)(__float_as_uint(a2) & 1023u);

    // T covers: fp16 key rounding (2^-11), accum/slop, index-packing (2^-14 rel)
    const float kmx = __uint_as_float(g_km[c]);
    const float g = kmx * sxn[t];
    const float T = 2.0f * (fmaf(5.9e-4f, g, 3.1e-5f * kmx * kmx) + 5e-4f);

    int bestj = c1;
    bool full = false;
    if (a1 - a2 > T) {
        // certain
    } else if (a1 - a3 > T) {
        // true argmax provably in {c1, c2}: exact fp32 pair compare
        const float* kc0 = keys + (size_t)c * J * DK;
        const float4* xr = (const float4*)(x + fi);
        const float4* k1 = (const float4*)(kc0 + (size_t)c1 * DK);
        const float4* k2 = (const float4*)(kc0 + (size_t)c2 * DK);
        float sA_ = 0.f, kkA = 0.f, sB_ = 0.f, kkB = 0.f;
#pragma unroll
        for (int q = 0; q < 4; q++) {
            float4 xv = xr[q], ka = k1[q], kb = k2[q];
            sA_ += xv.x * ka.x + xv.y * ka.y + xv.z * ka.z + xv.w * ka.w;
            kkA += ka.x * ka.x + ka.y * ka.y + ka.z * ka.z + ka.w * ka.w;
            sB_ += xv.x * kb.x + xv.y * kb.y + xv.z * kb.z + xv.w * kb.w;
            kkB += kb.x * kb.x + kb.y * kb.y + kb.z * kb.z + kb.w * kb.w;
        }
        float ea = sA_ - 0.5f * kkA, eb = sB_ - 0.5f * kkB;
        bestj = (ea > eb) ? c1 : ((eb > ea) ? c2 : min(c1, c2));
    } else {
        full = true;
    }

    unsigned m = __ballot_sync(0xffffffffu, full);
    while (m) {
        int src = __ffs(m) - 1;
        m &= m - 1;
        int fs = __shfl_sync(0xffffffffu, fi, src);
        float xv[16];
        const float4* xr = (const float4*)(x + fs);
#pragma unroll
        for (int q = 0; q < 4; q++) {
            float4 v = xr[q];
            xv[4 * q] = v.x; xv[4 * q + 1] = v.y; xv[4 * q + 2] = v.z; xv[4 * q + 3] = v.w;
        }
        const float* kc0 = keys + (size_t)c * J * DK;
        float bs = -FLT_MAX; int bj = 0;
        for (int q = 0; q < 32; q++) {
            int j = q * 32 + lane;
            const float4* kr = (const float4*)(kc0 + (size_t)j * DK);
            float dot = 0.f, kk = 0.f;
#pragma unroll
            for (int u = 0; u < 4; u++) {
                float4 kv = kr[u];
                dot += xv[4 * u] * kv.x + xv[4 * u + 1] * kv.y + xv[4 * u + 2] * kv.z + xv[4 * u + 3] * kv.w;
                kk  += kv.x * kv.x + kv.y * kv.y + kv.z * kv.z + kv.w * kv.w;
            }
            float s = dot - 0.5f * kk;
            if (s > bs) { bs = s; bj = j; }  // ascending j, strict >
        }
#pragma unroll
        for (int off = 16; off > 0; off >>= 1) {
            float os = __shfl_down_sync(0xffffffffu, bs, off);
            int   oj = __shfl_down_sync(0xffffffffu, bj, off);
            if (os > bs || (os == bs && oj < bj)) { bs = os; bj = oj; }
        }
        int win = __shfl_sync(0xffffffffu, bj, 0);
        if (lane == src) bestj = win;
    }

    // Epilogue: qv gather + EMA atomics
    {
        const int j = bestj;
        const float4* vs = (const float4*)(values + (size_t)(c * J + j) * DK);
        float4* qd = (float4*)(out + OFF_QV + fi);
#pragma unroll
        for (int q = 0; q < 4; q++) qd[q] = vs[q];

        atomicAdd(out + OFF_CS + c * J + j, OMD);
        float* ka = out + OFF_KA + (size_t)(c * J + j) * DK;
        const float4* xr = (const float4*)(x + fi);
#pragma unroll
        for (int q = 0; q < 4; q++) {
            float4 v = xr[q];
            atomicAdd(ka + 4 * q,     OMD * v.x);
            atomicAdd(ka + 4 * q + 1, OMD * v.y);
            atomicAdd(ka + 4 * q + 2, OMD * v.z);
            atomicAdd(ka + 4 * q + 3, OMD * v.w);
        }
    }
}

// ---------------- kernel 2: finalize new_keys --------------------------------
__global__ __launch_bounds__(256) void k_final(float* __restrict__ out) {
    __shared__ float sred[256];
    const int c = blockIdx.x, t = threadIdx.x;
    const float* ncs = out + OFF_CS + c * J;

    float part = 0.f;
    for (int j = t; j < J; j += 256) part += ncs[j];
    sred[t] = part;
    __syncthreads();
    for (int s = 128; s > 0; s >>= 1) {
        if (t < s) sred[t] += sred[t + s];
        __syncthreads();
    }
    const float tot = sred[0];
    const float scale = tot / (tot + (float)J * EPSV);

    for (int j = t; j < J; j += 256) {
        float inv = 1.0f / ((ncs[j] + EPSV) * scale);
        const float4* ka = (const float4*)(out + OFF_KA + (size_t)(c * J + j) * DK);
        float4* nk = (float4*)(out + OFF_KEYS + (size_t)(c * J + j) * DK);
#pragma unroll
        for (int q = 0; q < 4; q++) {
            float4 v = ka[q];
            v.x *= inv; v.y *= inv; v.z *= inv; v.w *= inv;
            nk[q] = v;
        }
    }
}

extern "C" void kernel_launch(void* const* d_in, const int* in_sizes, int n_in,
                              void* d_out, int out_size) {
    const float* x        = (const float*)d_in[0];
    const float* keys     = (const float*)d_in[1];
    const float* values   = (const float*)d_in[2];
    const float* keys_avg = (const float*)d_in[3];
    const float* cs       = (const float*)d_in[4];
    float* out = (float*)d_out;

    k_prep<<<1344, 256>>>(keys, keys_avg, cs, out);
    k_screen<<<1024, 256>>>(x, keys, values, out);
    k_final<<<64, 256>>>(out);
}

// round 12
// speedup vs baseline: 1.2492x; 1.2492x over previous
#include <cuda_runtime.h>
#include <cuda_bf16.h>
#include <cstdint>
#include <cfloat>

// KeyValueBottleneck: b=32, C=64, n=64, dk=dv=16, J=1024
// out = concat(qv[2097152], new_keys[1048576], new_cluster_size[65536], new_keys_avg[1048576])

#define DECAY 0.95f
#define OMD   0.05f
#define EPSV  1e-5f

constexpr int Cc = 64, Nn = 64, DK = 16, J = 1024;
constexpr int OFF_QV   = 0;
constexpr int OFF_KEYS = 2097152;
constexpr int OFF_CS   = OFF_KEYS + Cc * J * DK;  // 3145728
constexpr int OFF_KA   = OFF_CS + Cc * J;         // 3211264

// ---------------- scratch (device globals; no allocation) --------------------
// per key row (64 B): 4 blocks of 16 B indexed by lc:
//   blk[lc] = { khi_word[lc], khi_word[lc+4], klo_word[lc], klo_word[lc+4] }
// (word i = bf16 pair for dims 2i, 2i+1) -> one LDS.128 per mma B fragment.
__device__ uint4 g_kb[(size_t)Cc * J * 4];   // 4 MB
__device__ float    g_kk[Cc * J];            // -0.5*||k||^2 (fp32, exact bias)
__device__ unsigned g_km[Cc];                // max ||k|| per channel (bits)

__device__ __forceinline__ uint32_t pkbf(float a, float b) {
    __nv_bfloat16 ha = __float2bfloat16(a), hb = __float2bfloat16(b);
    return (uint32_t)__bfloat16_as_ushort(ha) | ((uint32_t)__bfloat16_as_ushort(hb) << 16);
}

// classic tensor-core MMA: m16n8k16, bf16 x bf16 -> fp32 (sm_80+)
__device__ __forceinline__ void mma16816(float* d, const uint32_t* a,
                                         uint32_t b0, uint32_t b1) {
    asm volatile(
        "mma.sync.aligned.m16n8k16.row.col.f32.bf16.bf16.f32 "
        "{%0,%1,%2,%3}, {%4,%5,%6,%7}, {%8,%9}, {%0,%1,%2,%3};"
        : "+f"(d[0]), "+f"(d[1]), "+f"(d[2]), "+f"(d[3])
        : "r"(a[0]), "r"(a[1]), "r"(a[2]), "r"(a[3]), "r"(b0), "r"(b1));
}

__device__ __forceinline__ uint32_t smem_u32(const void* p) {
    uint32_t a;
    asm("{ .reg .u64 t; cvta.to.shared.u64 t, %1; cvt.u32.u64 %0, t; }" : "=r"(a) : "l"(p));
    return a;
}
__device__ __forceinline__ void cpasync16(uint32_t smem, const void* g) {
    asm volatile("cp.async.cg.shared.global [%0], [%1], 16;" :: "r"(smem), "l"(g));
}
#define CP_COMMIT() asm volatile("cp.async.commit_group;" ::: "memory")
#define CP_WAIT(n)  asm volatile("cp.async.wait_group %0;" :: "n"(n) : "memory")

// ---------------- kernel 0: EMA seed (MLP=4) + key split-convert -------------
// grid 576 x 256:
//   blocks [0,256):   out_ka = DECAY*keys_avg, 4 strided float4/thread (MLP 4)
//   blocks [256,320): out_cs = DECAY*cs, 1 float4/thread
//   blocks [320,576): key rows, 1 thread/row (LDGs batched -> MLP 4)
__global__ __launch_bounds__(256) void k_prep(const float* __restrict__ keys,
                                              const float* __restrict__ keys_avg,
                                              const float* __restrict__ cs,
                                              float* __restrict__ out) {
    const int b = blockIdx.x, t = threadIdx.x;
    if (b < 256) {
        const float4* ka4 = (const float4*)keys_avg;
        float4* o4 = (float4*)out + OFF_KA / 4;
        int i = b * 256 + t;
        float4 v0 = ka4[i], v1 = ka4[i + 65536], v2 = ka4[i + 131072], v3 = ka4[i + 196608];
        v0.x *= DECAY; v0.y *= DECAY; v0.z *= DECAY; v0.w *= DECAY;
        v1.x *= DECAY; v1.y *= DECAY; v1.z *= DECAY; v1.w *= DECAY;
        v2.x *= DECAY; v2.y *= DECAY; v2.z *= DECAY; v2.w *= DECAY;
        v3.x *= DECAY; v3.y *= DECAY; v3.z *= DECAY; v3.w *= DECAY;
        o4[i] = v0; o4[i + 65536] = v1; o4[i + 131072] = v2; o4[i + 196608] = v3;
        return;
    }
    if (b < 320) {
        int i = (b - 256) * 256 + t;
        float4 v = ((const float4*)cs)[i];
        v.x *= DECAY; v.y *= DECAY; v.z *= DECAY; v.w *= DECAY;
        ((float4*)out)[OFF_CS / 4 + i] = v;
        return;
    }
    const int row = (b - 320) * 256 + t;   // 0..65535
    const float4* kr = (const float4*)(keys + (size_t)row * DK);
    float kv[16], kk = 0.f;
#pragma unroll
    for (int q = 0; q < 4; q++) {
        float4 v = kr[q];
        kv[4 * q] = v.x; kv[4 * q + 1] = v.y; kv[4 * q + 2] = v.z; kv[4 * q + 3] = v.w;
        kk += v.x * v.x + v.y * v.y + v.z * v.z + v.w * v.w;
    }
    uint32_t hi[8], lo[8];
#pragma unroll
    for (int d = 0; d < 8; d++) {
        float a = kv[2 * d], bv = kv[2 * d + 1];
        float ah = __bfloat162float(__float2bfloat16(a));
        float bh = __bfloat162float(__float2bfloat16(bv));
        hi[d] = pkbf(a, bv);
        lo[d] = pkbf(a - ah, bv - bh);
    }
    uint4* dst = g_kb + (size_t)row * 4;
#pragma unroll
    for (int lc = 0; lc < 4; lc++)
        dst[lc] = make_uint4(hi[lc], hi[lc + 4], lo[lc], lo[lc + 4]);
    g_kk[row] = -0.5f * kk;
    float mx = kk;
#pragma unroll
    for (int off = 16; off > 0; off >>= 1)
        mx = fmaxf(mx, __shfl_xor_sync(0xffffffffu, mx, off));
    if ((t & 31) == 0) atomicMax(&g_km[row >> 10], __float_as_uint(sqrtf(mx)));
}

// ---------------- kernel 1: split-bf16 3-MMA screen + exact fallback ---------
// (byte-identical to the proven 81us R10 screen)
__global__ __launch_bounds__(256) void k_screen(const float* __restrict__ x,
                                                const float* __restrict__ keys,
                                                const float* __restrict__ values,
                                                float* __restrict__ out) {
    __shared__ __align__(16) unsigned char sA[128 * 80];   // [xhi|xlo] rows, 80B stride
    __shared__ __align__(16) unsigned char sB[2][8192];    // dbl-buf 128-key chunks, 64B rows
    __shared__ float skk[J];
    __shared__ float sxn[128];
    __shared__ float sb1[128], sb2[128];
    __shared__ int   sbj[128];

    const int t = threadIdx.x, wid = t >> 5, lane = t & 31;
    const int c = blockIdx.x >> 4, mt = blockIdx.x & 15;
    const int lg = lane >> 2, lc = lane & 3;

    // convert x rows (threads 0..127) + load skk (all 256)
    if (t < 128) {
        const int i0 = mt * 128 + t;
        const int fidx = (((i0 >> 6) * Cc + c) * Nn + (i0 & 63)) * DK;
        const float4* xr = (const float4*)(x + fidx);
        float xv[16], n2 = 0.f;
#pragma unroll
        for (int q = 0; q < 4; q++) {
            float4 v = xr[q];
            xv[4 * q] = v.x; xv[4 * q + 1] = v.y; xv[4 * q + 2] = v.z; xv[4 * q + 3] = v.w;
            n2 += v.x * v.x + v.y * v.y + v.z * v.z + v.w * v.w;
        }
        uint32_t w[16];
#pragma unroll
        for (int d = 0; d < 8; d++) {
            float a = xv[2 * d], bv = xv[2 * d + 1];
            float ah = __bfloat162float(__float2bfloat16(a));
            float bh = __bfloat162float(__float2bfloat16(bv));
            w[d]     = pkbf(a, bv);           // xhi
            w[8 + d] = pkbf(a - ah, bv - bh); // xlo
        }
        uint4* dst = (uint4*)(sA + t * 80);
#pragma unroll
        for (int q = 0; q < 4; q++)
            dst[q] = make_uint4(w[4 * q], w[4 * q + 1], w[4 * q + 2], w[4 * q + 3]);
        sxn[t] = sqrtf(n2);
    }
    ((float4*)skk)[t] = ((const float4*)(g_kk + c * J))[t];

    // prefetch key chunk 0 (contiguous 8 KB)
    const uint32_t sb_base = smem_u32(sB);
    const char* kbase = (const char*)(g_kb + (size_t)c * J * 4);
    cpasync16(sb_base + t * 16,        kbase + t * 16);
    cpasync16(sb_base + t * 16 + 4096, kbase + t * 16 + 4096);
    CP_COMMIT();
    __syncthreads();

    // A fragments: afr[hi/lo][4], rows wid*16..+15
    uint32_t afr[2][4];
#pragma unroll
    for (int ks = 0; ks < 2; ks++) {
        int r0 = wid * 16 + lg;
        int bo = ks * 32 + lc * 4;
        afr[ks][0] = *(const uint32_t*)(sA + r0 * 80 + bo);
        afr[ks][1] = *(const uint32_t*)(sA + (r0 + 8) * 80 + bo);
        afr[ks][2] = *(const uint32_t*)(sA + r0 * 80 + bo + 16);
        afr[ks][3] = *(const uint32_t*)(sA + (r0 + 8) * 80 + bo + 16);
    }

    // per-parity top-2 values + top-1 index, per tracker (ti=0: row lg; ti=1: row lg+8)
    float v1e[2] = {-FLT_MAX, -FLT_MAX}, v1o[2] = {-FLT_MAX, -FLT_MAX};
    float v2e[2] = {-FLT_MAX, -FLT_MAX}, v2o[2] = {-FLT_MAX, -FLT_MAX};
    int   je[2]  = {0, 0},               jo[2]  = {0, 0};

    for (int ch = 0; ch < 8; ch++) {
        if (ch < 7) {
            const char* src = kbase + (size_t)(ch + 1) * 8192;
            uint32_t dstb = sb_base + ((ch + 1) & 1) * 8192;
            cpasync16(dstb + t * 16,        src + t * 16);
            cpasync16(dstb + t * 16 + 4096, src + t * 16 + 4096);
            CP_COMMIT();
            CP_WAIT(1);
        } else {
            CP_WAIT(0);
        }
        __syncthreads();

        const unsigned char* buf = sB[ch & 1] + lg * 64 + lc * 16;
#pragma unroll
        for (int jt = 0; jt < 16; jt++) {
            const uint4 bb = *(const uint4*)(buf + jt * 512);  // 8 rows * 64B
            const int j0 = ch * 128 + jt * 8 + lc * 2;
            const float2 bias = *(const float2*)(skk + j0);

            float d[4] = {bias.x, bias.y, bias.x, bias.y};
            mma16816(d, afr[0], bb.x, bb.y);   // xhi.khi
            mma16816(d, afr[1], bb.x, bb.y);   // xlo.khi
            mma16816(d, afr[0], bb.z, bb.w);   // xhi.klo

#pragma unroll
            for (int ti = 0; ti < 2; ti++) {
                const float s0 = d[2 * ti], s1 = d[2 * ti + 1];
                const bool p0 = s0 > v1e[ti];
                v2e[ti] = fmaxf(v2e[ti], fminf(s0, v1e[ti]));
                v1e[ti] = fmaxf(v1e[ti], s0);
                je[ti]  = p0 ? j0 : je[ti];
                const bool p1 = s1 > v1o[ti];
                v2o[ti] = fmaxf(v2o[ti], fminf(s1, v1o[ti]));
                v1o[ti] = fmaxf(v1o[ti], s1);
                jo[ti]  = p1 ? j0 + 1 : jo[ti];
            }
        }
        __syncthreads();
    }

    // merge parity classes within thread, then across the 4 lanes of each row-quad
    float V1[2], V2[2];
    int   Jb[2];
#pragma unroll
    for (int ti = 0; ti < 2; ti++) {
        const float rest = fmaxf(v2e[ti], v2o[ti]);
        if (v1o[ti] > v1e[ti]) {
            V1[ti] = v1o[ti]; Jb[ti] = jo[ti]; V2[ti] = fmaxf(v1e[ti], rest);
        } else {
            V1[ti] = v1e[ti]; Jb[ti] = je[ti]; V2[ti] = fmaxf(v1o[ti], rest);
        }
    }
#pragma unroll
    for (int mask = 1; mask <= 2; mask <<= 1) {
#pragma unroll
        for (int ti = 0; ti < 2; ti++) {
            float w1 = __shfl_xor_sync(0xffffffffu, V1[ti], mask);
            float w2 = __shfl_xor_sync(0xffffffffu, V2[ti], mask);
            int   i1 = __shfl_xor_sync(0xffffffffu, Jb[ti], mask);
            if (w1 > V1[ti] || (w1 == V1[ti] && i1 < Jb[ti])) {
                V2[ti] = fmaxf(V1[ti], w2);
                V1[ti] = w1; Jb[ti] = i1;
            } else {
                V2[ti] = fmaxf(V2[ti], w1);
            }
        }
    }
    if (lc == 0) {
#pragma unroll
        for (int ti = 0; ti < 2; ti++) {
            int r = wid * 16 + ti * 8 + lg;
            sb1[r] = V1[ti]; sb2[r] = V2[ti]; sbj[r] = Jb[ti];
        }
    }
    __syncthreads();

    if (t >= 128) return;  // threads 0..127 own points

    const int i = mt * 128 + t;
    const int fi = (((i >> 6) * Cc + c) * Nn + (i & 63)) * DK;
    int bestj = sbj[t];

    // certify: screen error <= 2^-18*||x||*||k|| + fp32 accum slop
    const float kmx = __uint_as_float(g_km[c]);
    const float bound = fmaf(1e-5f * kmx, sxn[t], 1e-4f);
    const bool amb = (sb1[t] - sb2[t]) <= 2.0f * bound;

    unsigned m = __ballot_sync(0xffffffffu, amb);
    while (m) {
        int src = __ffs(m) - 1;
        m &= m - 1;
        int fs = __shfl_sync(0xffffffffu, fi, src);
        float xv[16];
        const float4* xr = (const float4*)(x + fs);
#pragma unroll
        for (int q = 0; q < 4; q++) {
            float4 v = xr[q];
            xv[4 * q] = v.x; xv[4 * q + 1] = v.y; xv[4 * q + 2] = v.z; xv[4 * q + 3] = v.w;
        }
        const float* kc0 = keys + (size_t)c * J * DK;
        float bs = -FLT_MAX; int bj = 0;
        for (int q = 0; q < 32; q++) {
            int j = q * 32 + lane;
            const float4* kr = (const float4*)(kc0 + (size_t)j * DK);
            float dot = 0.f, kk = 0.f;
#pragma unroll
            for (int u = 0; u < 4; u++) {
                float4 kv = kr[u];
                dot += xv[4 * u] * kv.x + xv[4 * u + 1] * kv.y + xv[4 * u + 2] * kv.z + xv[4 * u + 3] * kv.w;
                kk  += kv.x * kv.x + kv.y * kv.y + kv.z * kv.z + kv.w * kv.w;
            }
            float s = dot - 0.5f * kk;
            if (s > bs) { bs = s; bj = j; }  // ascending j, strict >
        }
#pragma unroll
        for (int off = 16; off > 0; off >>= 1) {
            float os = __shfl_down_sync(0xffffffffu, bs, off);
            int   oj = __shfl_down_sync(0xffffffffu, bj, off);
            if (os > bs || (os == bs && oj < bj)) { bs = os; bj = oj; }
        }
        int win = __shfl_sync(0xffffffffu, bj, 0);
        if (lane == src) bestj = win;
    }

    // Epilogue: qv gather + EMA atomics
    {
        const int j = bestj;
        const float4* vs = (const float4*)(values + (size_t)(c * J + j) * DK);
        float4* qd = (float4*)(out + OFF_QV + fi);
#pragma unroll
        for (int q = 0; q < 4; q++) qd[q] = vs[q];

        atomicAdd(out + OFF_CS + c * J + j, OMD);
        float* ka = out + OFF_KA + (size_t)(c * J + j) * DK;
        const float4* xr = (const float4*)(x + fi);
#pragma unroll
        for (int q = 0; q < 4; q++) {
            float4 v = xr[q];
            atomicAdd(ka + 4 * q,     OMD * v.x);
            atomicAdd(ka + 4 * q + 1, OMD * v.y);
            atomicAdd(ka + 4 * q + 2, OMD * v.z);
            atomicAdd(ka + 4 * q + 3, OMD * v.w);
        }
    }
}

// ---------------- kernel 2: finalize new_keys (1 key/thread) -----------------
__global__ __launch_bounds__(1024) void k_final(float* __restrict__ out) {
    __shared__ float swred[32];
    const int c = blockIdx.x, t = threadIdx.x, lane = t & 31, w = t >> 5;
    const float* ncs = out + OFF_CS + c * J;

    float v = ncs[t];
    float s = v;
#pragma unroll
    for (int off = 16; off > 0; off >>= 1)
        s += __shfl_xor_sync(0xffffffffu, s, off);
    if (lane == 0) swred[w] = s;
    __syncthreads();
    if (w == 0) {
        float r = swred[lane];
#pragma unroll
        for (int off = 16; off > 0; off >>= 1)
            r += __shfl_xor_sync(0xffffffffu, r, off);
        if (lane == 0) swred[0] = r;
    }
    __syncthreads();
    const float tot = swred[0];
    const float scale = tot / (tot + (float)J * EPSV);

    const float inv = 1.0f / ((v + EPSV) * scale);
    const float4* ka = (const float4*)(out + OFF_KA + (size_t)(c * J + t) * DK);
    float4* nk = (float4*)(out + OFF_KEYS + (size_t)(c * J + t) * DK);
#pragma unroll
    for (int q = 0; q < 4; q++) {
        float4 u = ka[q];
        u.x *= inv; u.y *= inv; u.z *= inv; u.w *= inv;
        nk[q] = u;
    }
}

extern "C" void kernel_launch(void* const* d_in, const int* in_sizes, int n_in,
                              void* d_out, int out_size) {
    const float* x        = (const float*)d_in[0];
    const float* keys     = (const float*)d_in[1];
    const float* values   = (const float*)d_in[2];
    const float* keys_avg = (const float*)d_in[3];
    const float* cs       = (const float*)d_in[4];
    float* out = (float*)d_out;

    k_prep<<<576, 256>>>(keys, keys_avg, cs, out);
    k_screen<<<1024, 256>>>(x, keys, values, out);
    k_final<<<64, 1024>>>(out);
}